// round 1
// baseline (speedup 1.0000x reference)
#include <cuda_runtime.h>
#include <math.h>

#define BB 2
#define SS 2048
#define DM 1024
#define NH 16
#define HD 64
#define NEG_INF -1000000000.0f

// ---------------- scratch (device globals: allocation-free) ----------------
__device__ float g_tq[BB*SS*DM];   // x@Wq  [B,S,Dm]
__device__ float g_tk[BB*SS*DM];   // x@Wk
__device__ float g_tv[BB*SS*DM];   // x@Wv
__device__ float g_Q [BB*SS*DM];   // roped, [B,H,S,Hd]
__device__ float g_K [BB*SS*DM];
__device__ float g_V [BB*SS*DM];
__device__ float g_O [BB*SS*DM];   // attention out, [B,S,Dm]

// ---------------- SGEMM: C[M,N] = A[M,K] @ W[K,N], fp32 --------------------
// 64x64 block tile, BK=16, 256 threads, 4x4 per thread.
__global__ __launch_bounds__(256)
void sgemm_kernel(const float* __restrict__ A,
                  const float* __restrict__ W0,
                  const float* __restrict__ W1,
                  const float* __restrict__ W2,
                  float* __restrict__ C0,
                  float* __restrict__ C1,
                  float* __restrict__ C2,
                  int M, int N, int K)
{
    const float* __restrict__ W = (blockIdx.z == 0) ? W0 : ((blockIdx.z == 1) ? W1 : W2);
    float* __restrict__ C       = (blockIdx.z == 0) ? C0 : ((blockIdx.z == 1) ? C1 : C2);

    __shared__ float As[16][68];   // transposed: As[k][m], padded
    __shared__ float Bs[16][68];   // Bs[k][n], padded (row stride 272B, 16B-aligned)

    const int tid = threadIdx.x;
    const int tx  = tid & 15;
    const int ty  = tid >> 4;
    const int m0  = blockIdx.y * 64;
    const int n0  = blockIdx.x * 64;

    const int ar  = tid >> 2;      // 0..63 (A tile row)
    const int ac4 = tid & 3;       // which float4 in the 16-wide k slab
    const int br  = tid >> 4;      // 0..15 (B tile k-row)
    const int bc4 = tid & 15;      // which float4 in the 64-wide n slab

    float acc[4][4];
    #pragma unroll
    for (int i = 0; i < 4; i++)
        #pragma unroll
        for (int j = 0; j < 4; j++) acc[i][j] = 0.0f;

    for (int kt = 0; kt < K; kt += 16) {
        float4 a4 = *(const float4*)&A[(size_t)(m0 + ar) * K + kt + ac4 * 4];
        As[ac4*4 + 0][ar] = a4.x;
        As[ac4*4 + 1][ar] = a4.y;
        As[ac4*4 + 2][ar] = a4.z;
        As[ac4*4 + 3][ar] = a4.w;
        *(float4*)&Bs[br][bc4 * 4] =
            *(const float4*)&W[(size_t)(kt + br) * N + n0 + bc4 * 4];
        __syncthreads();

        #pragma unroll
        for (int k = 0; k < 16; k++) {
            float4 a = *(const float4*)&As[k][ty * 4];
            float4 b = *(const float4*)&Bs[k][tx * 4];
            acc[0][0] += a.x * b.x; acc[0][1] += a.x * b.y; acc[0][2] += a.x * b.z; acc[0][3] += a.x * b.w;
            acc[1][0] += a.y * b.x; acc[1][1] += a.y * b.y; acc[1][2] += a.y * b.z; acc[1][3] += a.y * b.w;
            acc[2][0] += a.z * b.x; acc[2][1] += a.z * b.y; acc[2][2] += a.z * b.z; acc[2][3] += a.z * b.w;
            acc[3][0] += a.w * b.x; acc[3][1] += a.w * b.y; acc[3][2] += a.w * b.z; acc[3][3] += a.w * b.w;
        }
        __syncthreads();
    }

    #pragma unroll
    for (int i = 0; i < 4; i++) {
        float4 o = make_float4(acc[i][0], acc[i][1], acc[i][2], acc[i][3]);
        *(float4*)&C[(size_t)(m0 + ty * 4 + i) * N + n0 + tx * 4] = o;
    }
}

// ---------------- RoPE + transpose [B,S,Dm] -> [B,H,S,Hd] ------------------
// blockIdx.y: 0 = Q (rope), 1 = K (rope), 2 = V (plain copy)
__global__ __launch_bounds__(256)
void rope_transpose_kernel()
{
    const int which = blockIdx.y;
    const float* __restrict__ src = (which == 0) ? g_tq : ((which == 1) ? g_tk : g_tv);
    float* __restrict__ dst       = (which == 0) ? g_Q  : ((which == 1) ? g_K  : g_V);

    int idx = blockIdx.x * 256 + threadIdx.x;   // [0, B*H*S*32)
    int j = idx & 31;
    int s = (idx >> 5) & (SS - 1);
    int h = (idx >> 16) & (NH - 1);
    int b = idx >> 20;

    size_t si = ((size_t)(b * SS + s)) * DM + h * HD;
    float t1 = src[si + j];
    float t2 = src[si + 32 + j];

    float o1, o2;
    if (which < 2) {
        // inv_freq = 10000^(-j/32); compute angle in double for accuracy
        double inv = exp(-(double)j * (9.210340371976184 / 32.0));
        double ang = (double)s * inv;
        double sn, cs;
        sincos(ang, &sn, &cs);
        float c = (float)cs, sf = (float)sn;
        o1 = t1 * c - t2 * sf;
        o2 = t1 * sf + t2 * c;
    } else {
        o1 = t1; o2 = t2;
    }
    size_t di = (((size_t)(b * NH + h)) * SS + s) * HD;
    dst[di + j]      = o1;
    dst[di + 32 + j] = o2;
}

// ---------------- Flash attention (fp32, causal, online softmax) -----------
// grid: (S/64, B*H). block: 256 (16x16). Q tile 64, K tile 32.
__global__ __launch_bounds__(256)
void attention_kernel(const float* __restrict__ mask)
{
    __shared__ float Qs[64][68];
    __shared__ float Ks[32][68];
    __shared__ float Vs[32][68];
    __shared__ float Ps[64][36];
    __shared__ float madd[32];

    const int tid = threadIdx.x;
    const int tx  = tid & 15;
    const int ty  = tid >> 4;
    const int qt  = blockIdx.x;
    const int bh  = blockIdx.y;
    const int b   = bh >> 4;
    const int h   = bh & 15;

    const float scale = 0.125f;  // 1/sqrt(64)
    const size_t base = (size_t)bh * SS * HD;

    // load Q tile (pre-scaled)
    {
        int r  = tid >> 2;
        int c4 = tid & 3;
        const float4* src = (const float4*)&g_Q[base + (size_t)(qt * 64 + r) * HD];
        float4* dstrow = (float4*)&Qs[r][0];
        #pragma unroll
        for (int u = 0; u < 4; u++) {
            float4 v = src[c4 + u * 4];
            v.x *= scale; v.y *= scale; v.z *= scale; v.w *= scale;
            dstrow[c4 + u * 4] = v;
        }
    }

    float acc[4][4];
    float m_i[4], l_i[4];
    #pragma unroll
    for (int i = 0; i < 4; i++) {
        m_i[i] = -1e30f; l_i[i] = 0.0f;
        #pragma unroll
        for (int j = 0; j < 4; j++) acc[i][j] = 0.0f;
    }

    const int kt_end = qt * 2 + 2;  // causal: keys <= qt*64+63
    for (int kt = 0; kt < kt_end; kt++) {
        __syncthreads();  // previous PV done before smem overwrite (also orders Qs)
        // load K,V tile (32 rows x 64)
        #pragma unroll
        for (int u = 0; u < 2; u++) {
            int id = tid + u * 256;
            int r  = id >> 4;       // 0..31
            int c4 = id & 15;
            *(float4*)&Ks[r][c4 * 4] =
                *(const float4*)&g_K[base + (size_t)(kt * 32 + r) * HD + c4 * 4];
            *(float4*)&Vs[r][c4 * 4] =
                *(const float4*)&g_V[base + (size_t)(kt * 32 + r) * HD + c4 * 4];
        }
        if (tid < 32) {
            float mv = mask[b * SS + kt * 32 + tid];
            madd[tid] = (1.0f - mv) * NEG_INF;
        }
        __syncthreads();

        // scores: rows q = ty*4+i, cols k = tx*2+j
        float sv[4][2];
        #pragma unroll
        for (int i = 0; i < 4; i++) { sv[i][0] = 0.0f; sv[i][1] = 0.0f; }
        #pragma unroll
        for (int kv4 = 0; kv4 < 16; kv4++) {
            float4 k0 = *(const float4*)&Ks[tx * 2 + 0][kv4 * 4];
            float4 k1 = *(const float4*)&Ks[tx * 2 + 1][kv4 * 4];
            #pragma unroll
            for (int i = 0; i < 4; i++) {
                float4 q = *(const float4*)&Qs[ty * 4 + i][kv4 * 4];
                sv[i][0] += q.x * k0.x + q.y * k0.y + q.z * k0.z + q.w * k0.w;
                sv[i][1] += q.x * k1.x + q.y * k1.y + q.z * k1.z + q.w * k1.w;
            }
        }

        // mask + online softmax update
        const int qg0 = qt * 64 + ty * 4;
        #pragma unroll
        for (int i = 0; i < 4; i++) {
            #pragma unroll
            for (int j = 0; j < 2; j++) {
                int kg = kt * 32 + tx * 2 + j;
                float sval = sv[i][j] + madd[tx * 2 + j];
                if (kg > qg0 + i) sval = NEG_INF;
                sv[i][j] = sval;
            }
            float mloc = fmaxf(sv[i][0], sv[i][1]);
            #pragma unroll
            for (int off = 1; off < 16; off <<= 1)
                mloc = fmaxf(mloc, __shfl_xor_sync(0xffffffffu, mloc, off));
            float mnew = fmaxf(m_i[i], mloc);
            float p0 = __expf(sv[i][0] - mnew);
            float p1 = __expf(sv[i][1] - mnew);
            Ps[ty * 4 + i][tx * 2 + 0] = p0;
            Ps[ty * 4 + i][tx * 2 + 1] = p1;
            float psum = p0 + p1;
            #pragma unroll
            for (int off = 1; off < 16; off <<= 1)
                psum += __shfl_xor_sync(0xffffffffu, psum, off);
            float alpha = __expf(m_i[i] - mnew);
            l_i[i] = l_i[i] * alpha + psum;
            m_i[i] = mnew;
            #pragma unroll
            for (int j = 0; j < 4; j++) acc[i][j] *= alpha;
        }
        __syncthreads();

        // PV: acc[i][j] += sum_kk Ps[q][kk] * Vs[kk][tx*4+j]
        #pragma unroll 8
        for (int kk = 0; kk < 32; kk++) {
            float4 vv = *(const float4*)&Vs[kk][tx * 4];
            #pragma unroll
            for (int i = 0; i < 4; i++) {
                float p = Ps[ty * 4 + i][kk];
                acc[i][0] += p * vv.x;
                acc[i][1] += p * vv.y;
                acc[i][2] += p * vv.z;
                acc[i][3] += p * vv.w;
            }
        }
    }

    // finalize + write [B,S,Dm]
    const int qg = qt * 64 + ty * 4;
    #pragma unroll
    for (int i = 0; i < 4; i++) {
        float invl = 1.0f / l_i[i];
        float4 o = make_float4(acc[i][0] * invl, acc[i][1] * invl,
                               acc[i][2] * invl, acc[i][3] * invl);
        *(float4*)&g_O[((size_t)(b * SS) + qg + i) * DM + h * HD + tx * 4] = o;
    }
}

// ---------------------------------------------------------------------------
extern "C" void kernel_launch(void* const* d_in, const int* in_sizes, int n_in,
                              void* d_out, int out_size)
{
    const float* x    = (const float*)d_in[0];
    const float* mask = (const float*)d_in[1];
    const float* Wq   = (const float*)d_in[2];
    const float* Wk   = (const float*)d_in[3];
    const float* Wv   = (const float*)d_in[4];
    const float* Wo   = (const float*)d_in[5];
    float* out = (float*)d_out;

    float *tq, *tk, *tv, *O;
    cudaGetSymbolAddress((void**)&tq, g_tq);
    cudaGetSymbolAddress((void**)&tk, g_tk);
    cudaGetSymbolAddress((void**)&tv, g_tv);
    cudaGetSymbolAddress((void**)&O,  g_O);

    const int M = BB * SS;   // 4096
    const int N = DM;        // 1024
    const int K = DM;        // 1024

    // 1) fused QKV projections
    sgemm_kernel<<<dim3(N / 64, M / 64, 3), 256>>>(x, Wq, Wk, Wv, tq, tk, tv, M, N, K);

    // 2) RoPE + transpose to [B,H,S,Hd]
    rope_transpose_kernel<<<dim3((BB * NH * SS * 32) / 256, 3), 256>>>();

    // 3) causal flash attention
    attention_kernel<<<dim3(SS / 64, BB * NH), 256>>>(mask);

    // 4) output projection
    sgemm_kernel<<<dim3(N / 64, M / 64, 1), 256>>>(O, Wo, Wo, Wo, out, out, out, M, N, K);
}

// round 3
// speedup vs baseline: 1.3122x; 1.3122x over previous
#include <cuda_runtime.h>
#include <cuda_bf16.h>
#include <math.h>
#include <stdint.h>

#define BB 2
#define SS 2048
#define DM 1024
#define NH 16
#define HD 64
#define NEG_INF -1000000000.0f

// ---------------- scratch (device globals: allocation-free) ----------------
__device__ float g_tq[BB*SS*DM];   // x@Wq  [B,S,Dm]
__device__ float g_tk[BB*SS*DM];
__device__ float g_tv[BB*SS*DM];
__device__ float g_Q [BB*SS*DM];   // roped, [B,H,S,Hd]
__device__ float g_K [BB*SS*DM];
__device__ float g_V [BB*SS*DM];
__device__ float g_O [BB*SS*DM];   // attention out, [B,S,Dm]

__device__ __nv_bfloat16 g_xhi[BB*SS*DM];       // activation split
__device__ __nv_bfloat16 g_xlo[BB*SS*DM];
__device__ __nv_bfloat16 g_wthi[4*DM*DM];       // W^T split: [z][N][K]
__device__ __nv_bfloat16 g_wtlo[4*DM*DM];

// ================= warp-MMA helpers (sm_103 base, no 'a' features) ==========
__device__ __forceinline__ uint32_t smem_u32(const void* p) {
    uint32_t a;
    asm("{ .reg .u64 t; cvta.to.shared.u64 t, %1; cvt.u32.u64 %0, t; }" : "=r"(a) : "l"(p));
    return a;
}
__device__ __forceinline__ void ldsm_x4(uint32_t* r, uint32_t addr) {
    asm volatile("ldmatrix.sync.aligned.m8n8.x4.shared.b16 {%0,%1,%2,%3}, [%4];"
                 : "=r"(r[0]), "=r"(r[1]), "=r"(r[2]), "=r"(r[3]) : "r"(addr));
}
__device__ __forceinline__ void mma_bf16(float* c, const uint32_t* a,
                                         uint32_t b0, uint32_t b1) {
    asm volatile(
        "mma.sync.aligned.m16n8k16.row.col.f32.bf16.bf16.f32 "
        "{%0,%1,%2,%3}, {%4,%5,%6,%7}, {%8,%9}, {%0,%1,%2,%3};"
        : "+f"(c[0]), "+f"(c[1]), "+f"(c[2]), "+f"(c[3])
        : "r"(a[0]), "r"(a[1]), "r"(a[2]), "r"(a[3]), "r"(b0), "r"(b1));
}

// ================= split / transpose kernels ================================
__global__ __launch_bounds__(256)
void split_kernel(const float* __restrict__ src,
                  __nv_bfloat16* __restrict__ hi,
                  __nv_bfloat16* __restrict__ lo)
{
    int i = (blockIdx.x * 256 + threadIdx.x) * 4;
    float4 v = *(const float4*)&src[i];
    __nv_bfloat16 h0 = __float2bfloat16(v.x);
    __nv_bfloat16 h1 = __float2bfloat16(v.y);
    __nv_bfloat16 h2 = __float2bfloat16(v.z);
    __nv_bfloat16 h3 = __float2bfloat16(v.w);
    __nv_bfloat16 l0 = __float2bfloat16(v.x - __bfloat162float(h0));
    __nv_bfloat16 l1 = __float2bfloat16(v.y - __bfloat162float(h1));
    __nv_bfloat16 l2 = __float2bfloat16(v.z - __bfloat162float(h2));
    __nv_bfloat16 l3 = __float2bfloat16(v.w - __bfloat162float(h3));
    *(__nv_bfloat162*)&hi[i]     = __nv_bfloat162(h0, h1);
    *(__nv_bfloat162*)&hi[i + 2] = __nv_bfloat162(h2, h3);
    *(__nv_bfloat162*)&lo[i]     = __nv_bfloat162(l0, l1);
    *(__nv_bfloat162*)&lo[i + 2] = __nv_bfloat162(l2, l3);
}

// W[K][N] fp32 -> Wt[z][N][K] bf16 hi/lo (transposed, split)
__global__ __launch_bounds__(256)
void wsplit_kernel(const float* __restrict__ Wq, const float* __restrict__ Wk,
                   const float* __restrict__ Wv, const float* __restrict__ Wo)
{
    __shared__ float tile[32][33];
    int z = blockIdx.z;
    const float* __restrict__ W = (z == 0) ? Wq : ((z == 1) ? Wk : ((z == 2) ? Wv : Wo));
    int n0 = blockIdx.x * 32;
    int k0 = blockIdx.y * 32;
    int tx = threadIdx.x & 31;
    int ty = threadIdx.x >> 5;   // 0..7
    #pragma unroll
    for (int i = 0; i < 4; i++) {
        int k = ty + i * 8;
        tile[k][tx] = W[(size_t)(k0 + k) * DM + n0 + tx];
    }
    __syncthreads();
    #pragma unroll
    for (int i = 0; i < 4; i++) {
        int n = ty + i * 8;
        float v = tile[tx][n];
        __nv_bfloat16 h = __float2bfloat16(v);
        __nv_bfloat16 l = __float2bfloat16(v - __bfloat162float(h));
        size_t di = ((size_t)z * DM + n0 + n) * DM + k0 + tx;
        g_wthi[di] = h;
        g_wtlo[di] = l;
    }
}

// ================= HMMA split-bf16 GEMM =====================================
// C[m,n] = sum_k A[m,k]*W[k,n] via (Ahi+Alo)*(Bhi+Blo), dropping lo*lo.
// Tile: BM=128, BN=128, BK=32. 256 threads (8 warps), warp tile 64x32.
#define GBM 128
#define GBN 128
#define GBK 32
#define GSTR 40            // bf16 elems per smem row (80B, conflict-free for ldmatrix)

__global__ __launch_bounds__(256)
void gemm_tc_kernel(const __nv_bfloat16* __restrict__ Ahi,
                    const __nv_bfloat16* __restrict__ Alo,
                    const __nv_bfloat16* __restrict__ Whi,  // [z][N][K]
                    const __nv_bfloat16* __restrict__ Wlo,
                    float* __restrict__ C0, float* __restrict__ C1,
                    float* __restrict__ C2)
{
    __shared__ __align__(16) __nv_bfloat16 sAh[GBM * GSTR];
    __shared__ __align__(16) __nv_bfloat16 sAl[GBM * GSTR];
    __shared__ __align__(16) __nv_bfloat16 sBh[GBN * GSTR];
    __shared__ __align__(16) __nv_bfloat16 sBl[GBN * GSTR];

    const int tid  = threadIdx.x;
    const int wid  = tid >> 5;
    const int lane = tid & 31;
    const int m0 = blockIdx.y * GBM;
    const int n0 = blockIdx.x * GBN;
    const int z  = blockIdx.z;
    const __nv_bfloat16* __restrict__ Wh = Whi + (size_t)z * DM * DM;
    const __nv_bfloat16* __restrict__ Wl = Wlo + (size_t)z * DM * DM;
    float* __restrict__ C = (z == 0) ? C0 : ((z == 1) ? C1 : C2);

    const int wm = wid & 1;        // 0..1 -> 64-row slab
    const int wn = wid >> 1;       // 0..3 -> 32-col slab

    // ldmatrix per-lane byte offset within a 16x16 tile region
    const int row_off = (lane & 7) + ((lane >> 3) & 1) * 8;
    const int kadd    = ((lane >> 4) & 1) * 8;
    const uint32_t lmoff = (uint32_t)(row_off * (GSTR * 2) + kadd * 2);

    const uint32_t sAh_b = smem_u32(sAh), sAl_b = smem_u32(sAl);
    const uint32_t sBh_b = smem_u32(sBh), sBl_b = smem_u32(sBl);

    // global load indexing: idx -> row r = idx>>2, 16B chunk c = idx&3
    const int r_a = tid >> 2;
    const int c_a = tid & 3;

    float acc[4][4][4];
    #pragma unroll
    for (int i = 0; i < 4; i++)
        #pragma unroll
        for (int j = 0; j < 4; j++)
            #pragma unroll
            for (int q = 0; q < 4; q++) acc[i][j][q] = 0.0f;

    for (int kc = 0; kc < DM / GBK; kc++) {
        const int k0 = kc * GBK;
        // load A/B tiles: 128 rows x 32 bf16 each, 16B per thread per iter
        #pragma unroll
        for (int it = 0; it < 2; it++) {
            int r = r_a + it * 64;
            uint32_t so = (uint32_t)(r * (GSTR * 2) + c_a * 16);
            size_t ga = (size_t)(m0 + r) * DM + k0 + c_a * 8;
            size_t gb = (size_t)(n0 + r) * DM + k0 + c_a * 8;
            *(uint4*)((char*)sAh + so) = *(const uint4*)&Ahi[ga];
            *(uint4*)((char*)sAl + so) = *(const uint4*)&Alo[ga];
            *(uint4*)((char*)sBh + so) = *(const uint4*)&Wh[gb];
            *(uint4*)((char*)sBl + so) = *(const uint4*)&Wl[gb];
        }
        __syncthreads();

        #pragma unroll
        for (int ks = 0; ks < 2; ks++) {
            uint32_t ah[4][4], al[4][4];
            #pragma unroll
            for (int mt = 0; mt < 4; mt++) {
                uint32_t aoff = (uint32_t)((wm * 64 + mt * 16) * (GSTR * 2) + ks * 32) + lmoff;
                ldsm_x4(ah[mt], sAh_b + aoff);
                ldsm_x4(al[mt], sAl_b + aoff);
            }
            uint32_t bh[2][4], bl[2][4];
            #pragma unroll
            for (int nt2 = 0; nt2 < 2; nt2++) {
                uint32_t boff = (uint32_t)((wn * 32 + nt2 * 16) * (GSTR * 2) + ks * 32) + lmoff;
                ldsm_x4(bh[nt2], sBh_b + boff);
                ldsm_x4(bl[nt2], sBl_b + boff);
            }
            #pragma unroll
            for (int mt = 0; mt < 4; mt++) {
                #pragma unroll
                for (int nt = 0; nt < 4; nt++) {
                    int n2 = nt >> 1, od = nt & 1;
                    mma_bf16(acc[mt][nt], ah[mt], bh[n2][od], bh[n2][od + 2]);
                    mma_bf16(acc[mt][nt], ah[mt], bl[n2][od], bl[n2][od + 2]);
                    mma_bf16(acc[mt][nt], al[mt], bh[n2][od], bh[n2][od + 2]);
                }
            }
        }
        __syncthreads();
    }

    // epilogue
    const int g   = lane >> 2;
    const int tig = lane & 3;
    #pragma unroll
    for (int mt = 0; mt < 4; mt++) {
        int row = m0 + wm * 64 + mt * 16 + g;
        #pragma unroll
        for (int nt = 0; nt < 4; nt++) {
            int col = n0 + wn * 32 + nt * 8 + tig * 2;
            *(float2*)&C[(size_t)row * DM + col]       = make_float2(acc[mt][nt][0], acc[mt][nt][1]);
            *(float2*)&C[(size_t)(row + 8) * DM + col] = make_float2(acc[mt][nt][2], acc[mt][nt][3]);
        }
    }
}

// ---------------- RoPE + transpose [B,S,Dm] -> [B,H,S,Hd] ------------------
__global__ __launch_bounds__(256)
void rope_transpose_kernel()
{
    const int which = blockIdx.y;
    const float* __restrict__ src = (which == 0) ? g_tq : ((which == 1) ? g_tk : g_tv);
    float* __restrict__ dst       = (which == 0) ? g_Q  : ((which == 1) ? g_K  : g_V);

    int idx = blockIdx.x * 256 + threadIdx.x;
    int j = idx & 31;
    int s = (idx >> 5) & (SS - 1);
    int h = (idx >> 16) & (NH - 1);
    int b = idx >> 20;

    size_t si = ((size_t)(b * SS + s)) * DM + h * HD;
    float t1 = src[si + j];
    float t2 = src[si + 32 + j];

    float o1, o2;
    if (which < 2) {
        double inv = exp(-(double)j * (9.210340371976184 / 32.0));
        double ang = (double)s * inv;
        double sn, cs;
        sincos(ang, &sn, &cs);
        float c = (float)cs, sf = (float)sn;
        o1 = t1 * c - t2 * sf;
        o2 = t1 * sf + t2 * c;
    } else {
        o1 = t1; o2 = t2;
    }
    size_t di = (((size_t)(b * NH + h)) * SS + s) * HD;
    dst[di + j]      = o1;
    dst[di + 32 + j] = o2;
}

// ---------------- Flash attention (fp32, causal, online softmax) -----------
__global__ __launch_bounds__(256)
void attention_kernel(const float* __restrict__ mask)
{
    __shared__ float Qs[64][68];
    __shared__ float Ks[32][68];
    __shared__ float Vs[32][68];
    __shared__ float Ps[64][36];
    __shared__ float madd[32];

    const int tid = threadIdx.x;
    const int tx  = tid & 15;
    const int ty  = tid >> 4;
    const int qt  = blockIdx.x;
    const int bh  = blockIdx.y;
    const int b   = bh >> 4;
    const int h   = bh & 15;

    const float scale = 0.125f;
    const size_t base = (size_t)bh * SS * HD;

    {
        int r  = tid >> 2;
        int c4 = tid & 3;
        const float4* src = (const float4*)&g_Q[base + (size_t)(qt * 64 + r) * HD];
        float4* dstrow = (float4*)&Qs[r][0];
        #pragma unroll
        for (int u = 0; u < 4; u++) {
            float4 v = src[c4 + u * 4];
            v.x *= scale; v.y *= scale; v.z *= scale; v.w *= scale;
            dstrow[c4 + u * 4] = v;
        }
    }

    float acc[4][4];
    float m_i[4], l_i[4];
    #pragma unroll
    for (int i = 0; i < 4; i++) {
        m_i[i] = -1e30f; l_i[i] = 0.0f;
        #pragma unroll
        for (int j = 0; j < 4; j++) acc[i][j] = 0.0f;
    }

    const int kt_end = qt * 2 + 2;
    for (int kt = 0; kt < kt_end; kt++) {
        __syncthreads();
        #pragma unroll
        for (int u = 0; u < 2; u++) {
            int id = tid + u * 256;
            int r  = id >> 4;
            int c4 = id & 15;
            *(float4*)&Ks[r][c4 * 4] =
                *(const float4*)&g_K[base + (size_t)(kt * 32 + r) * HD + c4 * 4];
            *(float4*)&Vs[r][c4 * 4] =
                *(const float4*)&g_V[base + (size_t)(kt * 32 + r) * HD + c4 * 4];
        }
        if (tid < 32) {
            float mv = mask[b * SS + kt * 32 + tid];
            madd[tid] = (1.0f - mv) * NEG_INF;
        }
        __syncthreads();

        float sv[4][2];
        #pragma unroll
        for (int i = 0; i < 4; i++) { sv[i][0] = 0.0f; sv[i][1] = 0.0f; }
        #pragma unroll
        for (int kv4 = 0; kv4 < 16; kv4++) {
            float4 k0 = *(const float4*)&Ks[tx * 2 + 0][kv4 * 4];
            float4 k1 = *(const float4*)&Ks[tx * 2 + 1][kv4 * 4];
            #pragma unroll
            for (int i = 0; i < 4; i++) {
                float4 q = *(const float4*)&Qs[ty * 4 + i][kv4 * 4];
                sv[i][0] += q.x * k0.x + q.y * k0.y + q.z * k0.z + q.w * k0.w;
                sv[i][1] += q.x * k1.x + q.y * k1.y + q.z * k1.z + q.w * k1.w;
            }
        }

        const int qg0 = qt * 64 + ty * 4;
        #pragma unroll
        for (int i = 0; i < 4; i++) {
            #pragma unroll
            for (int j = 0; j < 2; j++) {
                int kg = kt * 32 + tx * 2 + j;
                float sval = sv[i][j] + madd[tx * 2 + j];
                if (kg > qg0 + i) sval = NEG_INF;
                sv[i][j] = sval;
            }
            float mloc = fmaxf(sv[i][0], sv[i][1]);
            #pragma unroll
            for (int off = 1; off < 16; off <<= 1)
                mloc = fmaxf(mloc, __shfl_xor_sync(0xffffffffu, mloc, off));
            float mnew = fmaxf(m_i[i], mloc);
            float p0 = __expf(sv[i][0] - mnew);
            float p1 = __expf(sv[i][1] - mnew);
            Ps[ty * 4 + i][tx * 2 + 0] = p0;
            Ps[ty * 4 + i][tx * 2 + 1] = p1;
            float psum = p0 + p1;
            #pragma unroll
            for (int off = 1; off < 16; off <<= 1)
                psum += __shfl_xor_sync(0xffffffffu, psum, off);
            float alpha = __expf(m_i[i] - mnew);
            l_i[i] = l_i[i] * alpha + psum;
            m_i[i] = mnew;
            #pragma unroll
            for (int j = 0; j < 4; j++) acc[i][j] *= alpha;
        }
        __syncthreads();

        #pragma unroll 8
        for (int kk = 0; kk < 32; kk++) {
            float4 vv = *(const float4*)&Vs[kk][tx * 4];
            #pragma unroll
            for (int i = 0; i < 4; i++) {
                float p = Ps[ty * 4 + i][kk];
                acc[i][0] += p * vv.x;
                acc[i][1] += p * vv.y;
                acc[i][2] += p * vv.z;
                acc[i][3] += p * vv.w;
            }
        }
    }

    const int qg = qt * 64 + ty * 4;
    #pragma unroll
    for (int i = 0; i < 4; i++) {
        float invl = 1.0f / l_i[i];
        float4 o = make_float4(acc[i][0] * invl, acc[i][1] * invl,
                               acc[i][2] * invl, acc[i][3] * invl);
        *(float4*)&g_O[((size_t)(b * SS) + qg + i) * DM + h * HD + tx * 4] = o;
    }
}

// ---------------------------------------------------------------------------
extern "C" void kernel_launch(void* const* d_in, const int* in_sizes, int n_in,
                              void* d_out, int out_size)
{
    const float* x    = (const float*)d_in[0];
    const float* mask = (const float*)d_in[1];
    const float* Wq   = (const float*)d_in[2];
    const float* Wk   = (const float*)d_in[3];
    const float* Wv   = (const float*)d_in[4];
    const float* Wo   = (const float*)d_in[5];
    float* out = (float*)d_out;

    float *tq, *tk, *tv, *O;
    __nv_bfloat16 *xhi, *xlo, *wthi, *wtlo;
    cudaGetSymbolAddress((void**)&tq, g_tq);
    cudaGetSymbolAddress((void**)&tk, g_tk);
    cudaGetSymbolAddress((void**)&tv, g_tv);
    cudaGetSymbolAddress((void**)&O,  g_O);
    cudaGetSymbolAddress((void**)&xhi, g_xhi);
    cudaGetSymbolAddress((void**)&xlo, g_xlo);
    cudaGetSymbolAddress((void**)&wthi, g_wthi);
    cudaGetSymbolAddress((void**)&wtlo, g_wtlo);

    const int M = BB * SS;   // 4096
    const int NELEM = BB * SS * DM;

    // 0) split inputs to bf16 hi/lo; transpose+split weights
    split_kernel<<<NELEM / 1024, 256>>>(x, xhi, xlo);
    wsplit_kernel<<<dim3(DM / 32, DM / 32, 4), 256>>>(Wq, Wk, Wv, Wo);

    // 1) fused QKV projections (HMMA split-bf16)
    gemm_tc_kernel<<<dim3(DM / GBN, M / GBM, 3), 256>>>(
        xhi, xlo, wthi, wtlo, tq, tk, tv);

    // 2) RoPE + transpose to [B,H,S,Hd]
    rope_transpose_kernel<<<dim3((BB * NH * SS * 32) / 256, 3), 256>>>();

    // 3) causal flash attention (fp32)
    attention_kernel<<<dim3(SS / 64, BB * NH), 256>>>(mask);

    // 4) split attention output, then O projection
    split_kernel<<<NELEM / 1024, 256>>>(O, xhi, xlo);
    gemm_tc_kernel<<<dim3(DM / GBN, M / GBM, 1), 256>>>(
        xhi, xlo, wthi + 3 * (size_t)DM * DM, wtlo + 3 * (size_t)DM * DM,
        out, out, out);
}

// round 4
// speedup vs baseline: 3.0452x; 2.3207x over previous
#include <cuda_runtime.h>
#include <cuda_bf16.h>
#include <math.h>
#include <stdint.h>

#define BB 2
#define SS 2048
#define DM 1024
#define NH 16
#define HD 64
#define NEG_INF -1000000000.0f

// ---------------- scratch (device globals: allocation-free) ----------------
__device__ float g_tq[BB*SS*DM];   // x@Wq  [B,S,Dm]
__device__ float g_tk[BB*SS*DM];
__device__ float g_tv[BB*SS*DM];
__device__ float g_O [BB*SS*DM];   // attention out, [B,S,Dm]

__device__ __nv_bfloat16 g_xhi[BB*SS*DM];       // activation split
__device__ __nv_bfloat16 g_xlo[BB*SS*DM];
__device__ __nv_bfloat16 g_wthi[4*DM*DM];       // W^T split: [z][N][K]
__device__ __nv_bfloat16 g_wtlo[4*DM*DM];

__device__ __nv_bfloat16 g_Qhi[BB*NH*SS*HD];    // [B,H,S,Hd], pre-scaled
__device__ __nv_bfloat16 g_Qlo[BB*NH*SS*HD];
__device__ __nv_bfloat16 g_Khi[BB*NH*SS*HD];
__device__ __nv_bfloat16 g_Klo[BB*NH*SS*HD];
__device__ __nv_bfloat16 g_Vthi[BB*NH*HD*SS];   // [B,H,Hd,S] (transposed)
__device__ __nv_bfloat16 g_Vtlo[BB*NH*HD*SS];

__device__ float g_cos[SS*32];
__device__ float g_sin[SS*32];

// ================= warp-MMA helpers (sm_103 base, no 'a' features) ==========
__device__ __forceinline__ uint32_t smem_u32(const void* p) {
    uint32_t a;
    asm("{ .reg .u64 t; cvta.to.shared.u64 t, %1; cvt.u32.u64 %0, t; }" : "=r"(a) : "l"(p));
    return a;
}
__device__ __forceinline__ void ldsm_x4(uint32_t* r, uint32_t addr) {
    asm volatile("ldmatrix.sync.aligned.m8n8.x4.shared.b16 {%0,%1,%2,%3}, [%4];"
                 : "=r"(r[0]), "=r"(r[1]), "=r"(r[2]), "=r"(r[3]) : "r"(addr));
}
__device__ __forceinline__ void mma_bf16(float* c, const uint32_t* a,
                                         uint32_t b0, uint32_t b1) {
    asm volatile(
        "mma.sync.aligned.m16n8k16.row.col.f32.bf16.bf16.f32 "
        "{%0,%1,%2,%3}, {%4,%5,%6,%7}, {%8,%9}, {%0,%1,%2,%3};"
        : "+f"(c[0]), "+f"(c[1]), "+f"(c[2]), "+f"(c[3])
        : "r"(a[0]), "r"(a[1]), "r"(a[2]), "r"(a[3]), "r"(b0), "r"(b1));
}
__device__ __forceinline__ uint32_t packh(__nv_bfloat16 a, __nv_bfloat16 b) {
    return ((uint32_t)__bfloat16_as_ushort(b) << 16) | (uint32_t)__bfloat16_as_ushort(a);
}

// ================= split / weight-prep kernels ==============================
__global__ __launch_bounds__(256)
void split_kernel(const float* __restrict__ src,
                  __nv_bfloat16* __restrict__ hi,
                  __nv_bfloat16* __restrict__ lo)
{
    int i = (blockIdx.x * 256 + threadIdx.x) * 4;
    float4 v = *(const float4*)&src[i];
    __nv_bfloat16 h0 = __float2bfloat16(v.x);
    __nv_bfloat16 h1 = __float2bfloat16(v.y);
    __nv_bfloat16 h2 = __float2bfloat16(v.z);
    __nv_bfloat16 h3 = __float2bfloat16(v.w);
    __nv_bfloat16 l0 = __float2bfloat16(v.x - __bfloat162float(h0));
    __nv_bfloat16 l1 = __float2bfloat16(v.y - __bfloat162float(h1));
    __nv_bfloat16 l2 = __float2bfloat16(v.z - __bfloat162float(h2));
    __nv_bfloat16 l3 = __float2bfloat16(v.w - __bfloat162float(h3));
    *(__nv_bfloat162*)&hi[i]     = __nv_bfloat162(h0, h1);
    *(__nv_bfloat162*)&hi[i + 2] = __nv_bfloat162(h2, h3);
    *(__nv_bfloat162*)&lo[i]     = __nv_bfloat162(l0, l1);
    *(__nv_bfloat162*)&lo[i + 2] = __nv_bfloat162(l2, l3);
}

__global__ __launch_bounds__(256)
void wsplit_kernel(const float* __restrict__ Wq, const float* __restrict__ Wk,
                   const float* __restrict__ Wv, const float* __restrict__ Wo)
{
    __shared__ float tile[32][33];
    int z = blockIdx.z;
    const float* __restrict__ W = (z == 0) ? Wq : ((z == 1) ? Wk : ((z == 2) ? Wv : Wo));
    int n0 = blockIdx.x * 32;
    int k0 = blockIdx.y * 32;
    int tx = threadIdx.x & 31;
    int ty = threadIdx.x >> 5;
    #pragma unroll
    for (int i = 0; i < 4; i++) {
        int k = ty + i * 8;
        tile[k][tx] = W[(size_t)(k0 + k) * DM + n0 + tx];
    }
    __syncthreads();
    #pragma unroll
    for (int i = 0; i < 4; i++) {
        int n = ty + i * 8;
        float v = tile[tx][n];
        __nv_bfloat16 h = __float2bfloat16(v);
        __nv_bfloat16 l = __float2bfloat16(v - __bfloat162float(h));
        size_t di = ((size_t)z * DM + n0 + n) * DM + k0 + tx;
        g_wthi[di] = h;
        g_wtlo[di] = l;
    }
}

// ================= HMMA split-bf16 GEMM =====================================
#define GBM 128
#define GBN 128
#define GBK 32
#define GSTR 40

__global__ __launch_bounds__(256)
void gemm_tc_kernel(const __nv_bfloat16* __restrict__ Ahi,
                    const __nv_bfloat16* __restrict__ Alo,
                    const __nv_bfloat16* __restrict__ Whi,
                    const __nv_bfloat16* __restrict__ Wlo,
                    float* __restrict__ C0, float* __restrict__ C1,
                    float* __restrict__ C2)
{
    __shared__ __align__(16) __nv_bfloat16 sAh[GBM * GSTR];
    __shared__ __align__(16) __nv_bfloat16 sAl[GBM * GSTR];
    __shared__ __align__(16) __nv_bfloat16 sBh[GBN * GSTR];
    __shared__ __align__(16) __nv_bfloat16 sBl[GBN * GSTR];

    const int tid  = threadIdx.x;
    const int wid  = tid >> 5;
    const int lane = tid & 31;
    const int m0 = blockIdx.y * GBM;
    const int n0 = blockIdx.x * GBN;
    const int z  = blockIdx.z;
    const __nv_bfloat16* __restrict__ Wh = Whi + (size_t)z * DM * DM;
    const __nv_bfloat16* __restrict__ Wl = Wlo + (size_t)z * DM * DM;
    float* __restrict__ C = (z == 0) ? C0 : ((z == 1) ? C1 : C2);

    const int wm = wid & 1;
    const int wn = wid >> 1;

    const int row_off = (lane & 7) + ((lane >> 3) & 1) * 8;
    const int kadd    = ((lane >> 4) & 1) * 8;
    const uint32_t lmoff = (uint32_t)(row_off * (GSTR * 2) + kadd * 2);

    const uint32_t sAh_b = smem_u32(sAh), sAl_b = smem_u32(sAl);
    const uint32_t sBh_b = smem_u32(sBh), sBl_b = smem_u32(sBl);

    const int r_a = tid >> 2;
    const int c_a = tid & 3;

    float acc[4][4][4];
    #pragma unroll
    for (int i = 0; i < 4; i++)
        #pragma unroll
        for (int j = 0; j < 4; j++)
            #pragma unroll
            for (int q = 0; q < 4; q++) acc[i][j][q] = 0.0f;

    for (int kc = 0; kc < DM / GBK; kc++) {
        const int k0 = kc * GBK;
        #pragma unroll
        for (int it = 0; it < 2; it++) {
            int r = r_a + it * 64;
            uint32_t so = (uint32_t)(r * (GSTR * 2) + c_a * 16);
            size_t ga = (size_t)(m0 + r) * DM + k0 + c_a * 8;
            size_t gb = (size_t)(n0 + r) * DM + k0 + c_a * 8;
            *(uint4*)((char*)sAh + so) = *(const uint4*)&Ahi[ga];
            *(uint4*)((char*)sAl + so) = *(const uint4*)&Alo[ga];
            *(uint4*)((char*)sBh + so) = *(const uint4*)&Wh[gb];
            *(uint4*)((char*)sBl + so) = *(const uint4*)&Wl[gb];
        }
        __syncthreads();

        #pragma unroll
        for (int ks = 0; ks < 2; ks++) {
            uint32_t ah[4][4], al[4][4];
            #pragma unroll
            for (int mt = 0; mt < 4; mt++) {
                uint32_t aoff = (uint32_t)((wm * 64 + mt * 16) * (GSTR * 2) + ks * 32) + lmoff;
                ldsm_x4(ah[mt], sAh_b + aoff);
                ldsm_x4(al[mt], sAl_b + aoff);
            }
            uint32_t bh[2][4], bl[2][4];
            #pragma unroll
            for (int nt2 = 0; nt2 < 2; nt2++) {
                uint32_t boff = (uint32_t)((wn * 32 + nt2 * 16) * (GSTR * 2) + ks * 32) + lmoff;
                ldsm_x4(bh[nt2], sBh_b + boff);
                ldsm_x4(bl[nt2], sBl_b + boff);
            }
            #pragma unroll
            for (int mt = 0; mt < 4; mt++) {
                #pragma unroll
                for (int nt = 0; nt < 4; nt++) {
                    int n2 = nt >> 1, od = nt & 1;
                    mma_bf16(acc[mt][nt], ah[mt], bh[n2][od], bh[n2][od + 2]);
                    mma_bf16(acc[mt][nt], ah[mt], bl[n2][od], bl[n2][od + 2]);
                    mma_bf16(acc[mt][nt], al[mt], bh[n2][od], bh[n2][od + 2]);
                }
            }
        }
        __syncthreads();
    }

    const int g   = lane >> 2;
    const int tig = lane & 3;
    #pragma unroll
    for (int mt = 0; mt < 4; mt++) {
        int row = m0 + wm * 64 + mt * 16 + g;
        #pragma unroll
        for (int nt = 0; nt < 4; nt++) {
            int col = n0 + wn * 32 + nt * 8 + tig * 2;
            *(float2*)&C[(size_t)row * DM + col]       = make_float2(acc[mt][nt][0], acc[mt][nt][1]);
            *(float2*)&C[(size_t)(row + 8) * DM + col] = make_float2(acc[mt][nt][2], acc[mt][nt][3]);
        }
    }
}

// ---------------- trig table (double precision, tiny) ----------------------
__global__ __launch_bounds__(256)
void trig_kernel()
{
    int idx = blockIdx.x * 256 + threadIdx.x;   // [0, SS*32)
    int s = idx >> 5, j = idx & 31;
    double inv = exp(-(double)j * (9.210340371976184 / 32.0));
    double ang = (double)s * inv;
    double sn, cs;
    sincos(ang, &sn, &cs);
    g_cos[idx] = (float)cs;
    g_sin[idx] = (float)sn;
}

// ---------------- RoPE + transpose + split: Q, K ----------------------------
// [B,S,Dm] fp32 -> [B,H,S,Hd] bf16 hi/lo. Q pre-scaled by 1/sqrt(Hd).
__global__ __launch_bounds__(256)
void ropeqk_kernel()
{
    const int which = blockIdx.y;   // 0 = Q, 1 = K
    const float* __restrict__ src = (which == 0) ? g_tq : g_tk;
    __nv_bfloat16* __restrict__ dhi = (which == 0) ? g_Qhi : g_Khi;
    __nv_bfloat16* __restrict__ dlo = (which == 0) ? g_Qlo : g_Klo;
    const float scale = (which == 0) ? 0.125f : 1.0f;

    int idx = blockIdx.x * 256 + threadIdx.x;
    int j = idx & 31;
    int s = (idx >> 5) & (SS - 1);
    int h = (idx >> 16) & (NH - 1);
    int b = idx >> 20;

    size_t si = ((size_t)(b * SS + s)) * DM + h * HD;
    float t1 = src[si + j];
    float t2 = src[si + 32 + j];
    float c  = g_cos[s * 32 + j];
    float sn = g_sin[s * 32 + j];
    float o1 = (t1 * c - t2 * sn) * scale;
    float o2 = (t1 * sn + t2 * c) * scale;

    __nv_bfloat16 h1 = __float2bfloat16(o1);
    __nv_bfloat16 h2 = __float2bfloat16(o2);
    __nv_bfloat16 l1 = __float2bfloat16(o1 - __bfloat162float(h1));
    __nv_bfloat16 l2 = __float2bfloat16(o2 - __bfloat162float(h2));

    size_t di = (((size_t)(b * NH + h)) * SS + s) * HD;
    dhi[di + j]      = h1;
    dhi[di + 32 + j] = h2;
    dlo[di + j]      = l1;
    dlo[di + 32 + j] = l2;
}

// ---------------- V transpose + split: [B,S,Dm] -> [B,H,Hd,S] ---------------
__global__ __launch_bounds__(256)
void vtrans_kernel()
{
    __shared__ float tile[32][65];
    const int st = blockIdx.x;    // s tile (32 rows)
    const int h  = blockIdx.y;
    const int b  = blockIdx.z;
    const int tid = threadIdx.x;

    const float* __restrict__ src = g_tv + ((size_t)(b * SS + st * 32)) * DM + h * HD;
    #pragma unroll
    for (int i = 0; i < 8; i++) {
        int idx = tid + i * 256;
        int r = idx >> 6, c = idx & 63;
        tile[r][c] = src[(size_t)r * DM + c];
    }
    __syncthreads();
    #pragma unroll
    for (int i = 0; i < 8; i++) {
        int idx = tid + i * 256;
        int c = idx >> 5, r = idx & 31;
        float v = tile[r][c];
        __nv_bfloat16 hh = __float2bfloat16(v);
        __nv_bfloat16 ll = __float2bfloat16(v - __bfloat162float(hh));
        size_t di = ((size_t)(b * NH + h) * HD + c) * SS + st * 32 + r;
        g_Vthi[di] = hh;
        g_Vtlo[di] = ll;
    }
}

// ---------------- HMMA split-bf16 flash attention ---------------------------
// grid (32 qtiles, 32 bh), 128 threads (4 warps), warp = 16 q rows.
// Q tile 64, K tile 64. Causal. Online softmax in registers.
#define ASTR 72   // bf16 row stride (144B, odd 16B-granule count -> conflict-free ldmatrix)

__global__ __launch_bounds__(128)
void attention_tc_kernel(const float* __restrict__ mask)
{
    __shared__ __align__(16) __nv_bfloat16 sKh[64 * ASTR];
    __shared__ __align__(16) __nv_bfloat16 sKl[64 * ASTR];
    __shared__ __align__(16) __nv_bfloat16 sVh[64 * ASTR];
    __shared__ __align__(16) __nv_bfloat16 sVl[64 * ASTR];
    __shared__ float madd[64];

    const int tid  = threadIdx.x;
    const int wid  = tid >> 5;
    const int lane = tid & 31;
    const int qt = gridDim.x - 1 - blockIdx.x;   // big tiles first
    const int bh = blockIdx.y;
    const int b  = bh >> 4;
    const int h  = bh & 15;

    const size_t baseqk = (size_t)bh * SS * HD;
    const size_t basev  = (size_t)bh * HD * SS;

    const int row_off = (lane & 7) + ((lane >> 3) & 1) * 8;
    const int kadd    = ((lane >> 4) & 1) * 8;
    const uint32_t lmoff = (uint32_t)(row_off * (ASTR * 2) + kadd * 2);

    const uint32_t sKh_b = smem_u32(sKh), sKl_b = smem_u32(sKl);
    const uint32_t sVh_b = smem_u32(sVh), sVl_b = smem_u32(sVl);

    // ---- stage Q tile into sKh/sKl, load fragments to registers ----
    #pragma unroll
    for (int i = 0; i < 4; i++) {
        int idx = tid + i * 128;
        int r = idx >> 3, c8 = idx & 7;
        uint32_t so = (uint32_t)(r * (ASTR * 2) + c8 * 16);
        size_t gi = baseqk + (size_t)(qt * 64 + r) * HD + c8 * 8;
        *(uint4*)((char*)sKh + so) = *(const uint4*)&g_Qhi[gi];
        *(uint4*)((char*)sKl + so) = *(const uint4*)&g_Qlo[gi];
    }
    __syncthreads();
    uint32_t qh[4][4], ql[4][4];
    #pragma unroll
    for (int kc = 0; kc < 4; kc++) {
        uint32_t aoff = (uint32_t)((wid * 16) * (ASTR * 2) + kc * 32) + lmoff;
        ldsm_x4(qh[kc], sKh_b + aoff);
        ldsm_x4(ql[kc], sKl_b + aoff);
    }
    __syncthreads();

    float o[8][4];
    #pragma unroll
    for (int nt = 0; nt < 8; nt++)
        #pragma unroll
        for (int q = 0; q < 4; q++) o[nt][q] = 0.0f;
    float m0 = -1e30f, m1 = -1e30f, l0 = 0.0f, l1 = 0.0f;

    const int qg0 = qt * 64 + wid * 16 + (lane >> 2);   // row r global q index

    for (int kt = 0; kt <= qt; kt++) {
        // ---- load K tile [64 keys x 64 hd] and Vt tile [64 hd x 64 keys] ----
        #pragma unroll
        for (int i = 0; i < 4; i++) {
            int idx = tid + i * 128;
            int r = idx >> 3, c8 = idx & 7;
            uint32_t so = (uint32_t)(r * (ASTR * 2) + c8 * 16);
            size_t gk = baseqk + (size_t)(kt * 64 + r) * HD + c8 * 8;
            size_t gv = basev + (size_t)r * SS + kt * 64 + c8 * 8;
            *(uint4*)((char*)sKh + so) = *(const uint4*)&g_Khi[gk];
            *(uint4*)((char*)sKl + so) = *(const uint4*)&g_Klo[gk];
            *(uint4*)((char*)sVh + so) = *(const uint4*)&g_Vthi[gv];
            *(uint4*)((char*)sVl + so) = *(const uint4*)&g_Vtlo[gv];
        }
        if (tid < 64) {
            float mv = mask[b * SS + kt * 64 + tid];
            madd[tid] = (1.0f - mv) * NEG_INF;
        }
        __syncthreads();

        // ---- S = Q K^T (split: qh*kh + qh*kl + ql*kh) ----
        float s[8][4];
        #pragma unroll
        for (int nt = 0; nt < 8; nt++)
            #pragma unroll
            for (int q = 0; q < 4; q++) s[nt][q] = 0.0f;

        #pragma unroll
        for (int kc = 0; kc < 4; kc++) {
            uint32_t kh[4][4], kl[4][4];
            #pragma unroll
            for (int np = 0; np < 4; np++) {
                uint32_t boff = (uint32_t)((np * 16) * (ASTR * 2) + kc * 32) + lmoff;
                ldsm_x4(kh[np], sKh_b + boff);
                ldsm_x4(kl[np], sKl_b + boff);
            }
            #pragma unroll
            for (int nt = 0; nt < 8; nt++) {
                int np = nt >> 1, od = nt & 1;
                mma_bf16(s[nt], qh[kc], kh[np][od], kh[np][od + 2]);
                mma_bf16(s[nt], qh[kc], kl[np][od], kl[np][od + 2]);
                mma_bf16(s[nt], ql[kc], kh[np][od], kh[np][od + 2]);
            }
        }

        // ---- mask + online softmax ----
        const bool diag = (kt == qt);
        #pragma unroll
        for (int nt = 0; nt < 8; nt++) {
            int c0 = nt * 8 + (lane & 3) * 2;
            float ma0 = madd[c0], ma1 = madd[c0 + 1];
            s[nt][0] += ma0; s[nt][1] += ma1;
            s[nt][2] += ma0; s[nt][3] += ma1;
            if (diag) {
                int kg = kt * 64 + c0;
                if (kg     > qg0)     s[nt][0] = NEG_INF;
                if (kg + 1 > qg0)     s[nt][1] = NEG_INF;
                if (kg     > qg0 + 8) s[nt][2] = NEG_INF;
                if (kg + 1 > qg0 + 8) s[nt][3] = NEG_INF;
            }
        }
        float mx0 = -1e30f, mx1 = -1e30f;
        #pragma unroll
        for (int nt = 0; nt < 8; nt++) {
            mx0 = fmaxf(mx0, fmaxf(s[nt][0], s[nt][1]));
            mx1 = fmaxf(mx1, fmaxf(s[nt][2], s[nt][3]));
        }
        mx0 = fmaxf(mx0, __shfl_xor_sync(0xffffffffu, mx0, 1));
        mx0 = fmaxf(mx0, __shfl_xor_sync(0xffffffffu, mx0, 2));
        mx1 = fmaxf(mx1, __shfl_xor_sync(0xffffffffu, mx1, 1));
        mx1 = fmaxf(mx1, __shfl_xor_sync(0xffffffffu, mx1, 2));
        float mn0 = fmaxf(m0, mx0), mn1 = fmaxf(m1, mx1);
        float a0 = __expf(m0 - mn0), a1 = __expf(m1 - mn1);
        m0 = mn0; m1 = mn1;

        float ps0 = 0.0f, ps1 = 0.0f;
        #pragma unroll
        for (int nt = 0; nt < 8; nt++) {
            s[nt][0] = __expf(s[nt][0] - mn0);
            s[nt][1] = __expf(s[nt][1] - mn0);
            s[nt][2] = __expf(s[nt][2] - mn1);
            s[nt][3] = __expf(s[nt][3] - mn1);
            ps0 += s[nt][0] + s[nt][1];
            ps1 += s[nt][2] + s[nt][3];
        }
        ps0 += __shfl_xor_sync(0xffffffffu, ps0, 1);
        ps0 += __shfl_xor_sync(0xffffffffu, ps0, 2);
        ps1 += __shfl_xor_sync(0xffffffffu, ps1, 1);
        ps1 += __shfl_xor_sync(0xffffffffu, ps1, 2);
        l0 = l0 * a0 + ps0;
        l1 = l1 * a1 + ps1;
        #pragma unroll
        for (int nt = 0; nt < 8; nt++) {
            o[nt][0] *= a0; o[nt][1] *= a0;
            o[nt][2] *= a1; o[nt][3] *= a1;
        }

        // ---- O += P V (split: ph*vh + ph*vl + pl*vh) ----
        #pragma unroll
        for (int t = 0; t < 4; t++) {
            // P fragments straight from registers (C-layout == A-layout)
            __nv_bfloat16 h0 = __float2bfloat16(s[2*t][0]);
            __nv_bfloat16 h1 = __float2bfloat16(s[2*t][1]);
            __nv_bfloat16 h2 = __float2bfloat16(s[2*t][2]);
            __nv_bfloat16 h3 = __float2bfloat16(s[2*t][3]);
            __nv_bfloat16 h4 = __float2bfloat16(s[2*t+1][0]);
            __nv_bfloat16 h5 = __float2bfloat16(s[2*t+1][1]);
            __nv_bfloat16 h6 = __float2bfloat16(s[2*t+1][2]);
            __nv_bfloat16 h7 = __float2bfloat16(s[2*t+1][3]);
            uint32_t ph[4], pl[4];
            ph[0] = packh(h0, h1);
            ph[1] = packh(h2, h3);
            ph[2] = packh(h4, h5);
            ph[3] = packh(h6, h7);
            pl[0] = packh(__float2bfloat16(s[2*t][0]   - __bfloat162float(h0)),
                          __float2bfloat16(s[2*t][1]   - __bfloat162float(h1)));
            pl[1] = packh(__float2bfloat16(s[2*t][2]   - __bfloat162float(h2)),
                          __float2bfloat16(s[2*t][3]   - __bfloat162float(h3)));
            pl[2] = packh(__float2bfloat16(s[2*t+1][0] - __bfloat162float(h4)),
                          __float2bfloat16(s[2*t+1][1] - __bfloat162float(h5)));
            pl[3] = packh(__float2bfloat16(s[2*t+1][2] - __bfloat162float(h6)),
                          __float2bfloat16(s[2*t+1][3] - __bfloat162float(h7)));

            uint32_t vh[4][4], vl[4][4];
            #pragma unroll
            for (int np = 0; np < 4; np++) {
                uint32_t voff = (uint32_t)((np * 16) * (ASTR * 2) + t * 32) + lmoff;
                ldsm_x4(vh[np], sVh_b + voff);
                ldsm_x4(vl[np], sVl_b + voff);
            }
            #pragma unroll
            for (int nt = 0; nt < 8; nt++) {
                int np = nt >> 1, od = nt & 1;
                mma_bf16(o[nt], ph, vh[np][od], vh[np][od + 2]);
                mma_bf16(o[nt], ph, vl[np][od], vl[np][od + 2]);
                mma_bf16(o[nt], pl, vh[np][od], vh[np][od + 2]);
            }
        }
        __syncthreads();
    }

    // ---- finalize + write [B,S,Dm] ----
    float il0 = 1.0f / l0, il1 = 1.0f / l1;
    const int row = qt * 64 + wid * 16 + (lane >> 2);
    #pragma unroll
    for (int nt = 0; nt < 8; nt++) {
        int col = h * HD + nt * 8 + (lane & 3) * 2;
        *(float2*)&g_O[((size_t)(b * SS) + row) * DM + col] =
            make_float2(o[nt][0] * il0, o[nt][1] * il0);
        *(float2*)&g_O[((size_t)(b * SS) + row + 8) * DM + col] =
            make_float2(o[nt][2] * il1, o[nt][3] * il1);
    }
}

// ---------------------------------------------------------------------------
extern "C" void kernel_launch(void* const* d_in, const int* in_sizes, int n_in,
                              void* d_out, int out_size)
{
    const float* x    = (const float*)d_in[0];
    const float* mask = (const float*)d_in[1];
    const float* Wq   = (const float*)d_in[2];
    const float* Wk   = (const float*)d_in[3];
    const float* Wv   = (const float*)d_in[4];
    const float* Wo   = (const float*)d_in[5];
    float* out = (float*)d_out;

    float *tq, *tk, *tv, *O;
    __nv_bfloat16 *xhi, *xlo, *wthi, *wtlo;
    cudaGetSymbolAddress((void**)&tq, g_tq);
    cudaGetSymbolAddress((void**)&tk, g_tk);
    cudaGetSymbolAddress((void**)&tv, g_tv);
    cudaGetSymbolAddress((void**)&O,  g_O);
    cudaGetSymbolAddress((void**)&xhi, g_xhi);
    cudaGetSymbolAddress((void**)&xlo, g_xlo);
    cudaGetSymbolAddress((void**)&wthi, g_wthi);
    cudaGetSymbolAddress((void**)&wtlo, g_wtlo);

    const int M = BB * SS;   // 4096
    const int NELEM = BB * SS * DM;

    // 0) prep: input split, weight transpose+split, trig table
    split_kernel<<<NELEM / 1024, 256>>>(x, xhi, xlo);
    wsplit_kernel<<<dim3(DM / 32, DM / 32, 4), 256>>>(Wq, Wk, Wv, Wo);
    trig_kernel<<<(SS * 32) / 256, 256>>>();

    // 1) fused QKV projections (HMMA split-bf16)
    gemm_tc_kernel<<<dim3(DM / GBN, M / GBM, 3), 256>>>(
        xhi, xlo, wthi, wtlo, tq, tk, tv);

    // 2) RoPE (table-based) + transpose + split for Q,K; V transpose + split
    ropeqk_kernel<<<dim3((BB * NH * SS * 32) / 256, 2), 256>>>();
    vtrans_kernel<<<dim3(SS / 32, NH, BB), 256>>>();

    // 3) causal flash attention (HMMA split-bf16)
    attention_tc_kernel<<<dim3(SS / 64, BB * NH), 128>>>(mask);

    // 4) split attention output, then O projection
    split_kernel<<<NELEM / 1024, 256>>>(O, xhi, xlo);
    gemm_tc_kernel<<<dim3(DM / GBN, M / GBM, 1), 256>>>(
        xhi, xlo, wthi + 3 * (size_t)DM * DM, wtlo + 3 * (size_t)DM * DM,
        out, out, out);
}

// round 5
// speedup vs baseline: 3.1128x; 1.0222x over previous
#include <cuda_runtime.h>
#include <cuda_bf16.h>
#include <math.h>
#include <stdint.h>

#define BB 2
#define SS 2048
#define DM 1024
#define NH 16
#define HD 64
#define NEG_INF -1000000000.0f

// ---------------- scratch (device globals: allocation-free) ----------------
__device__ float g_tq[BB*SS*DM];   // x@Wq  [B,S,Dm]
__device__ float g_tk[BB*SS*DM];
__device__ float g_tv[BB*SS*DM];

__device__ __nv_bfloat16 g_xhi[BB*SS*DM];       // activation split
__device__ __nv_bfloat16 g_xlo[BB*SS*DM];
__device__ __nv_bfloat16 g_wthi[4*DM*DM];       // W^T split: [z][N][K]
__device__ __nv_bfloat16 g_wtlo[4*DM*DM];

__device__ __nv_bfloat16 g_Qhi[BB*NH*SS*HD];    // [B,H,S,Hd], pre-scaled
__device__ __nv_bfloat16 g_Qlo[BB*NH*SS*HD];
__device__ __nv_bfloat16 g_Khi[BB*NH*SS*HD];
__device__ __nv_bfloat16 g_Klo[BB*NH*SS*HD];
__device__ __nv_bfloat16 g_Vthi[BB*NH*HD*SS];   // [B,H,Hd,S] (transposed)
__device__ __nv_bfloat16 g_Vtlo[BB*NH*HD*SS];

__device__ float g_cos[SS*32];
__device__ float g_sin[SS*32];

// ================= warp-MMA helpers (sm_103 base, no 'a' features) ==========
__device__ __forceinline__ uint32_t smem_u32(const void* p) {
    uint32_t a;
    asm("{ .reg .u64 t; cvta.to.shared.u64 t, %1; cvt.u32.u64 %0, t; }" : "=r"(a) : "l"(p));
    return a;
}
__device__ __forceinline__ void ldsm_x4(uint32_t* r, uint32_t addr) {
    asm volatile("ldmatrix.sync.aligned.m8n8.x4.shared.b16 {%0,%1,%2,%3}, [%4];"
                 : "=r"(r[0]), "=r"(r[1]), "=r"(r[2]), "=r"(r[3]) : "r"(addr));
}
__device__ __forceinline__ void mma_bf16(float* c, const uint32_t* a,
                                         uint32_t b0, uint32_t b1) {
    asm volatile(
        "mma.sync.aligned.m16n8k16.row.col.f32.bf16.bf16.f32 "
        "{%0,%1,%2,%3}, {%4,%5,%6,%7}, {%8,%9}, {%0,%1,%2,%3};"
        : "+f"(c[0]), "+f"(c[1]), "+f"(c[2]), "+f"(c[3])
        : "r"(a[0]), "r"(a[1]), "r"(a[2]), "r"(a[3]), "r"(b0), "r"(b1));
}
__device__ __forceinline__ uint32_t packh(__nv_bfloat16 a, __nv_bfloat16 b) {
    return ((uint32_t)__bfloat16_as_ushort(b) << 16) | (uint32_t)__bfloat16_as_ushort(a);
}
__device__ __forceinline__ void cp_async16(uint32_t saddr, const void* gaddr) {
    asm volatile("cp.async.cg.shared.global [%0], [%1], 16;"
                 :: "r"(saddr), "l"(gaddr) : "memory");
}
__device__ __forceinline__ void cp_commit() {
    asm volatile("cp.async.commit_group;" ::: "memory");
}
template<int N> __device__ __forceinline__ void cp_wait() {
    asm volatile("cp.async.wait_group %0;" :: "n"(N) : "memory");
}

// ================= split / weight-prep kernels ==============================
__global__ __launch_bounds__(256)
void split_kernel(const float* __restrict__ src,
                  __nv_bfloat16* __restrict__ hi,
                  __nv_bfloat16* __restrict__ lo)
{
    int i = (blockIdx.x * 256 + threadIdx.x) * 4;
    float4 v = *(const float4*)&src[i];
    __nv_bfloat16 h0 = __float2bfloat16(v.x);
    __nv_bfloat16 h1 = __float2bfloat16(v.y);
    __nv_bfloat16 h2 = __float2bfloat16(v.z);
    __nv_bfloat16 h3 = __float2bfloat16(v.w);
    __nv_bfloat16 l0 = __float2bfloat16(v.x - __bfloat162float(h0));
    __nv_bfloat16 l1 = __float2bfloat16(v.y - __bfloat162float(h1));
    __nv_bfloat16 l2 = __float2bfloat16(v.z - __bfloat162float(h2));
    __nv_bfloat16 l3 = __float2bfloat16(v.w - __bfloat162float(h3));
    *(__nv_bfloat162*)&hi[i]     = __nv_bfloat162(h0, h1);
    *(__nv_bfloat162*)&hi[i + 2] = __nv_bfloat162(h2, h3);
    *(__nv_bfloat162*)&lo[i]     = __nv_bfloat162(l0, l1);
    *(__nv_bfloat162*)&lo[i + 2] = __nv_bfloat162(l2, l3);
}

__global__ __launch_bounds__(256)
void wsplit_kernel(const float* __restrict__ Wq, const float* __restrict__ Wk,
                   const float* __restrict__ Wv, const float* __restrict__ Wo)
{
    __shared__ float tile[32][33];
    int z = blockIdx.z;
    const float* __restrict__ W = (z == 0) ? Wq : ((z == 1) ? Wk : ((z == 2) ? Wv : Wo));
    int n0 = blockIdx.x * 32;
    int k0 = blockIdx.y * 32;
    int tx = threadIdx.x & 31;
    int ty = threadIdx.x >> 5;
    #pragma unroll
    for (int i = 0; i < 4; i++) {
        int k = ty + i * 8;
        tile[k][tx] = W[(size_t)(k0 + k) * DM + n0 + tx];
    }
    __syncthreads();
    #pragma unroll
    for (int i = 0; i < 4; i++) {
        int n = ty + i * 8;
        float v = tile[tx][n];
        __nv_bfloat16 h = __float2bfloat16(v);
        __nv_bfloat16 l = __float2bfloat16(v - __bfloat162float(h));
        size_t di = ((size_t)z * DM + n0 + n) * DM + k0 + tx;
        g_wthi[di] = h;
        g_wtlo[di] = l;
    }
}

// ================= HMMA split-bf16 GEMM (2-stage cp.async pipeline) =========
#define GBM 128
#define GBN 128
#define GBK 32
#define GSTR 40
#define STB (GBM * GSTR * 2)          // bytes per array per stage = 10240
#define GSM_TOTAL (8 * STB)           // 2 stages x 4 arrays = 81920

__global__ __launch_bounds__(256)
void gemm_tc_kernel(const __nv_bfloat16* __restrict__ Ahi,
                    const __nv_bfloat16* __restrict__ Alo,
                    const __nv_bfloat16* __restrict__ Whi,
                    const __nv_bfloat16* __restrict__ Wlo,
                    float* __restrict__ C0, float* __restrict__ C1,
                    float* __restrict__ C2)
{
    extern __shared__ __align__(16) char dsm[];

    const int tid  = threadIdx.x;
    const int wid  = tid >> 5;
    const int lane = tid & 31;
    const int m0 = blockIdx.y * GBM;
    const int n0 = blockIdx.x * GBN;
    const int z  = blockIdx.z;
    const __nv_bfloat16* __restrict__ Wh = Whi + (size_t)z * DM * DM;
    const __nv_bfloat16* __restrict__ Wl = Wlo + (size_t)z * DM * DM;
    float* __restrict__ C = (z == 0) ? C0 : ((z == 1) ? C1 : C2);

    const int wm = wid & 1;
    const int wn = wid >> 1;

    const int row_off = (lane & 7) + ((lane >> 3) & 1) * 8;
    const int kadd    = ((lane >> 4) & 1) * 8;
    const uint32_t lmoff = (uint32_t)(row_off * (GSTR * 2) + kadd * 2);

    const uint32_t sbase = smem_u32(dsm);
    const int r_a = tid >> 2;
    const int c_a = tid & 3;
    const uint32_t so0 = (uint32_t)(r_a * (GSTR * 2) + c_a * 16);
    const uint32_t so1 = (uint32_t)((r_a + 64) * (GSTR * 2) + c_a * 16);

    float acc[4][4][4];
    #pragma unroll
    for (int i = 0; i < 4; i++)
        #pragma unroll
        for (int j = 0; j < 4; j++)
            #pragma unroll
            for (int q = 0; q < 4; q++) acc[i][j][q] = 0.0f;

    const int NK = DM / GBK;   // 32

    // issue stage 0 loads
    {
        const int k0 = 0;
        uint32_t s0 = sbase;
        size_t ga0 = (size_t)(m0 + r_a) * DM + k0 + c_a * 8;
        size_t ga1 = (size_t)(m0 + r_a + 64) * DM + k0 + c_a * 8;
        size_t gb0 = (size_t)(n0 + r_a) * DM + k0 + c_a * 8;
        size_t gb1 = (size_t)(n0 + r_a + 64) * DM + k0 + c_a * 8;
        cp_async16(s0 + so0,           &Ahi[ga0]);
        cp_async16(s0 + so1,           &Ahi[ga1]);
        cp_async16(s0 + STB + so0,     &Alo[ga0]);
        cp_async16(s0 + STB + so1,     &Alo[ga1]);
        cp_async16(s0 + 2*STB + so0,   &Wh[gb0]);
        cp_async16(s0 + 2*STB + so1,   &Wh[gb1]);
        cp_async16(s0 + 3*STB + so0,   &Wl[gb0]);
        cp_async16(s0 + 3*STB + so1,   &Wl[gb1]);
        cp_commit();
    }

    for (int kc = 0; kc < NK; kc++) {
        if (kc + 1 < NK) {
            const int k0 = (kc + 1) * GBK;
            uint32_t s0 = sbase + (uint32_t)(((kc + 1) & 1) * 4 * STB);
            size_t ga0 = (size_t)(m0 + r_a) * DM + k0 + c_a * 8;
            size_t ga1 = (size_t)(m0 + r_a + 64) * DM + k0 + c_a * 8;
            size_t gb0 = (size_t)(n0 + r_a) * DM + k0 + c_a * 8;
            size_t gb1 = (size_t)(n0 + r_a + 64) * DM + k0 + c_a * 8;
            cp_async16(s0 + so0,           &Ahi[ga0]);
            cp_async16(s0 + so1,           &Ahi[ga1]);
            cp_async16(s0 + STB + so0,     &Alo[ga0]);
            cp_async16(s0 + STB + so1,     &Alo[ga1]);
            cp_async16(s0 + 2*STB + so0,   &Wh[gb0]);
            cp_async16(s0 + 2*STB + so1,   &Wh[gb1]);
            cp_async16(s0 + 3*STB + so0,   &Wl[gb0]);
            cp_async16(s0 + 3*STB + so1,   &Wl[gb1]);
            cp_commit();
            cp_wait<1>();
        } else {
            cp_wait<0>();
        }
        __syncthreads();

        const uint32_t st = sbase + (uint32_t)((kc & 1) * 4 * STB);
        const uint32_t sAh_b = st;
        const uint32_t sAl_b = st + STB;
        const uint32_t sBh_b = st + 2 * STB;
        const uint32_t sBl_b = st + 3 * STB;

        #pragma unroll
        for (int ks = 0; ks < 2; ks++) {
            uint32_t ah[4][4], al[4][4];
            #pragma unroll
            for (int mt = 0; mt < 4; mt++) {
                uint32_t aoff = (uint32_t)((wm * 64 + mt * 16) * (GSTR * 2) + ks * 32) + lmoff;
                ldsm_x4(ah[mt], sAh_b + aoff);
                ldsm_x4(al[mt], sAl_b + aoff);
            }
            uint32_t bh[2][4], bl[2][4];
            #pragma unroll
            for (int nt2 = 0; nt2 < 2; nt2++) {
                uint32_t boff = (uint32_t)((wn * 32 + nt2 * 16) * (GSTR * 2) + ks * 32) + lmoff;
                ldsm_x4(bh[nt2], sBh_b + boff);
                ldsm_x4(bl[nt2], sBl_b + boff);
            }
            #pragma unroll
            for (int mt = 0; mt < 4; mt++) {
                #pragma unroll
                for (int nt = 0; nt < 4; nt++) {
                    int n2 = nt >> 1, od = nt & 1;
                    mma_bf16(acc[mt][nt], ah[mt], bh[n2][od], bh[n2][od + 2]);
                    mma_bf16(acc[mt][nt], ah[mt], bl[n2][od], bl[n2][od + 2]);
                    mma_bf16(acc[mt][nt], al[mt], bh[n2][od], bh[n2][od + 2]);
                }
            }
        }
        __syncthreads();
    }

    const int g   = lane >> 2;
    const int tig = lane & 3;
    #pragma unroll
    for (int mt = 0; mt < 4; mt++) {
        int row = m0 + wm * 64 + mt * 16 + g;
        #pragma unroll
        for (int nt = 0; nt < 4; nt++) {
            int col = n0 + wn * 32 + nt * 8 + tig * 2;
            *(float2*)&C[(size_t)row * DM + col]       = make_float2(acc[mt][nt][0], acc[mt][nt][1]);
            *(float2*)&C[(size_t)(row + 8) * DM + col] = make_float2(acc[mt][nt][2], acc[mt][nt][3]);
        }
    }
}

// ---------------- trig table (double precision, tiny) ----------------------
__global__ __launch_bounds__(256)
void trig_kernel()
{
    int idx = blockIdx.x * 256 + threadIdx.x;   // [0, SS*32)
    int s = idx >> 5, j = idx & 31;
    double inv = exp(-(double)j * (9.210340371976184 / 32.0));
    double ang = (double)s * inv;
    double sn, cs;
    sincos(ang, &sn, &cs);
    g_cos[idx] = (float)cs;
    g_sin[idx] = (float)sn;
}

// ---------------- RoPE + transpose + split: Q, K ----------------------------
__global__ __launch_bounds__(256)
void ropeqk_kernel()
{
    const int which = blockIdx.y;   // 0 = Q, 1 = K
    const float* __restrict__ src = (which == 0) ? g_tq : g_tk;
    __nv_bfloat16* __restrict__ dhi = (which == 0) ? g_Qhi : g_Khi;
    __nv_bfloat16* __restrict__ dlo = (which == 0) ? g_Qlo : g_Klo;
    const float scale = (which == 0) ? 0.125f : 1.0f;

    int idx = blockIdx.x * 256 + threadIdx.x;
    int j = idx & 31;
    int s = (idx >> 5) & (SS - 1);
    int h = (idx >> 16) & (NH - 1);
    int b = idx >> 20;

    size_t si = ((size_t)(b * SS + s)) * DM + h * HD;
    float t1 = src[si + j];
    float t2 = src[si + 32 + j];
    float c  = g_cos[s * 32 + j];
    float sn = g_sin[s * 32 + j];
    float o1 = (t1 * c - t2 * sn) * scale;
    float o2 = (t1 * sn + t2 * c) * scale;

    __nv_bfloat16 h1 = __float2bfloat16(o1);
    __nv_bfloat16 h2 = __float2bfloat16(o2);
    __nv_bfloat16 l1 = __float2bfloat16(o1 - __bfloat162float(h1));
    __nv_bfloat16 l2 = __float2bfloat16(o2 - __bfloat162float(h2));

    size_t di = (((size_t)(b * NH + h)) * SS + s) * HD;
    dhi[di + j]      = h1;
    dhi[di + 32 + j] = h2;
    dlo[di + j]      = l1;
    dlo[di + 32 + j] = l2;
}

// ---------------- V transpose + split: [B,S,Dm] -> [B,H,Hd,S] ---------------
__global__ __launch_bounds__(256)
void vtrans_kernel()
{
    __shared__ float tile[32][65];
    const int st = blockIdx.x;
    const int h  = blockIdx.y;
    const int b  = blockIdx.z;
    const int tid = threadIdx.x;

    const float* __restrict__ src = g_tv + ((size_t)(b * SS + st * 32)) * DM + h * HD;
    #pragma unroll
    for (int i = 0; i < 8; i++) {
        int idx = tid + i * 256;
        int r = idx >> 6, c = idx & 63;
        tile[r][c] = src[(size_t)r * DM + c];
    }
    __syncthreads();
    #pragma unroll
    for (int i = 0; i < 8; i++) {
        int idx = tid + i * 256;
        int c = idx >> 5, r = idx & 31;
        float v = tile[r][c];
        __nv_bfloat16 hh = __float2bfloat16(v);
        __nv_bfloat16 ll = __float2bfloat16(v - __bfloat162float(hh));
        size_t di = ((size_t)(b * NH + h) * HD + c) * SS + st * 32 + r;
        g_Vthi[di] = hh;
        g_Vtlo[di] = ll;
    }
}

// ---------------- HMMA split-bf16 flash attention ---------------------------
#define ASTR 72

__global__ __launch_bounds__(128)
void attention_tc_kernel(const float* __restrict__ mask)
{
    __shared__ __align__(16) __nv_bfloat16 sKh[64 * ASTR];
    __shared__ __align__(16) __nv_bfloat16 sKl[64 * ASTR];
    __shared__ __align__(16) __nv_bfloat16 sVh[64 * ASTR];
    __shared__ __align__(16) __nv_bfloat16 sVl[64 * ASTR];
    __shared__ float madd[64];

    const int tid  = threadIdx.x;
    const int wid  = tid >> 5;
    const int lane = tid & 31;
    const int qt = gridDim.x - 1 - blockIdx.x;
    const int bh = blockIdx.y;
    const int b  = bh >> 4;
    const int h  = bh & 15;

    const size_t baseqk = (size_t)bh * SS * HD;
    const size_t basev  = (size_t)bh * HD * SS;

    const int row_off = (lane & 7) + ((lane >> 3) & 1) * 8;
    const int kadd    = ((lane >> 4) & 1) * 8;
    const uint32_t lmoff = (uint32_t)(row_off * (ASTR * 2) + kadd * 2);

    const uint32_t sKh_b = smem_u32(sKh), sKl_b = smem_u32(sKl);
    const uint32_t sVh_b = smem_u32(sVh), sVl_b = smem_u32(sVl);

    #pragma unroll
    for (int i = 0; i < 4; i++) {
        int idx = tid + i * 128;
        int r = idx >> 3, c8 = idx & 7;
        uint32_t so = (uint32_t)(r * (ASTR * 2) + c8 * 16);
        size_t gi = baseqk + (size_t)(qt * 64 + r) * HD + c8 * 8;
        *(uint4*)((char*)sKh + so) = *(const uint4*)&g_Qhi[gi];
        *(uint4*)((char*)sKl + so) = *(const uint4*)&g_Qlo[gi];
    }
    __syncthreads();
    uint32_t qh[4][4], ql[4][4];
    #pragma unroll
    for (int kc = 0; kc < 4; kc++) {
        uint32_t aoff = (uint32_t)((wid * 16) * (ASTR * 2) + kc * 32) + lmoff;
        ldsm_x4(qh[kc], sKh_b + aoff);
        ldsm_x4(ql[kc], sKl_b + aoff);
    }
    __syncthreads();

    float o[8][4];
    #pragma unroll
    for (int nt = 0; nt < 8; nt++)
        #pragma unroll
        for (int q = 0; q < 4; q++) o[nt][q] = 0.0f;
    float m0 = -1e30f, m1 = -1e30f, l0 = 0.0f, l1 = 0.0f;

    const int qg0 = qt * 64 + wid * 16 + (lane >> 2);

    for (int kt = 0; kt <= qt; kt++) {
        #pragma unroll
        for (int i = 0; i < 4; i++) {
            int idx = tid + i * 128;
            int r = idx >> 3, c8 = idx & 7;
            uint32_t so = (uint32_t)(r * (ASTR * 2) + c8 * 16);
            size_t gk = baseqk + (size_t)(kt * 64 + r) * HD + c8 * 8;
            size_t gv = basev + (size_t)r * SS + kt * 64 + c8 * 8;
            *(uint4*)((char*)sKh + so) = *(const uint4*)&g_Khi[gk];
            *(uint4*)((char*)sKl + so) = *(const uint4*)&g_Klo[gk];
            *(uint4*)((char*)sVh + so) = *(const uint4*)&g_Vthi[gv];
            *(uint4*)((char*)sVl + so) = *(const uint4*)&g_Vtlo[gv];
        }
        if (tid < 64) {
            float mv = mask[b * SS + kt * 64 + tid];
            madd[tid] = (1.0f - mv) * NEG_INF;
        }
        __syncthreads();

        float s[8][4];
        #pragma unroll
        for (int nt = 0; nt < 8; nt++)
            #pragma unroll
            for (int q = 0; q < 4; q++) s[nt][q] = 0.0f;

        #pragma unroll
        for (int kc = 0; kc < 4; kc++) {
            uint32_t kh[4][4], kl[4][4];
            #pragma unroll
            for (int np = 0; np < 4; np++) {
                uint32_t boff = (uint32_t)((np * 16) * (ASTR * 2) + kc * 32) + lmoff;
                ldsm_x4(kh[np], sKh_b + boff);
                ldsm_x4(kl[np], sKl_b + boff);
            }
            #pragma unroll
            for (int nt = 0; nt < 8; nt++) {
                int np = nt >> 1, od = nt & 1;
                mma_bf16(s[nt], qh[kc], kh[np][od], kh[np][od + 2]);
                mma_bf16(s[nt], qh[kc], kl[np][od], kl[np][od + 2]);
                mma_bf16(s[nt], ql[kc], kh[np][od], kh[np][od + 2]);
            }
        }

        const bool diag = (kt == qt);
        #pragma unroll
        for (int nt = 0; nt < 8; nt++) {
            int c0 = nt * 8 + (lane & 3) * 2;
            float ma0 = madd[c0], ma1 = madd[c0 + 1];
            s[nt][0] += ma0; s[nt][1] += ma1;
            s[nt][2] += ma0; s[nt][3] += ma1;
            if (diag) {
                int kg = kt * 64 + c0;
                if (kg     > qg0)     s[nt][0] = NEG_INF;
                if (kg + 1 > qg0)     s[nt][1] = NEG_INF;
                if (kg     > qg0 + 8) s[nt][2] = NEG_INF;
                if (kg + 1 > qg0 + 8) s[nt][3] = NEG_INF;
            }
        }
        float mx0 = -1e30f, mx1 = -1e30f;
        #pragma unroll
        for (int nt = 0; nt < 8; nt++) {
            mx0 = fmaxf(mx0, fmaxf(s[nt][0], s[nt][1]));
            mx1 = fmaxf(mx1, fmaxf(s[nt][2], s[nt][3]));
        }
        mx0 = fmaxf(mx0, __shfl_xor_sync(0xffffffffu, mx0, 1));
        mx0 = fmaxf(mx0, __shfl_xor_sync(0xffffffffu, mx0, 2));
        mx1 = fmaxf(mx1, __shfl_xor_sync(0xffffffffu, mx1, 1));
        mx1 = fmaxf(mx1, __shfl_xor_sync(0xffffffffu, mx1, 2));
        float mn0 = fmaxf(m0, mx0), mn1 = fmaxf(m1, mx1);
        float a0 = __expf(m0 - mn0), a1 = __expf(m1 - mn1);
        m0 = mn0; m1 = mn1;

        float ps0 = 0.0f, ps1 = 0.0f;
        #pragma unroll
        for (int nt = 0; nt < 8; nt++) {
            s[nt][0] = __expf(s[nt][0] - mn0);
            s[nt][1] = __expf(s[nt][1] - mn0);
            s[nt][2] = __expf(s[nt][2] - mn1);
            s[nt][3] = __expf(s[nt][3] - mn1);
            ps0 += s[nt][0] + s[nt][1];
            ps1 += s[nt][2] + s[nt][3];
        }
        ps0 += __shfl_xor_sync(0xffffffffu, ps0, 1);
        ps0 += __shfl_xor_sync(0xffffffffu, ps0, 2);
        ps1 += __shfl_xor_sync(0xffffffffu, ps1, 1);
        ps1 += __shfl_xor_sync(0xffffffffu, ps1, 2);
        l0 = l0 * a0 + ps0;
        l1 = l1 * a1 + ps1;
        #pragma unroll
        for (int nt = 0; nt < 8; nt++) {
            o[nt][0] *= a0; o[nt][1] *= a0;
            o[nt][2] *= a1; o[nt][3] *= a1;
        }

        #pragma unroll
        for (int t = 0; t < 4; t++) {
            __nv_bfloat16 h0 = __float2bfloat16(s[2*t][0]);
            __nv_bfloat16 h1 = __float2bfloat16(s[2*t][1]);
            __nv_bfloat16 h2 = __float2bfloat16(s[2*t][2]);
            __nv_bfloat16 h3 = __float2bfloat16(s[2*t][3]);
            __nv_bfloat16 h4 = __float2bfloat16(s[2*t+1][0]);
            __nv_bfloat16 h5 = __float2bfloat16(s[2*t+1][1]);
            __nv_bfloat16 h6 = __float2bfloat16(s[2*t+1][2]);
            __nv_bfloat16 h7 = __float2bfloat16(s[2*t+1][3]);
            uint32_t ph[4], pl[4];
            ph[0] = packh(h0, h1);
            ph[1] = packh(h2, h3);
            ph[2] = packh(h4, h5);
            ph[3] = packh(h6, h7);
            pl[0] = packh(__float2bfloat16(s[2*t][0]   - __bfloat162float(h0)),
                          __float2bfloat16(s[2*t][1]   - __bfloat162float(h1)));
            pl[1] = packh(__float2bfloat16(s[2*t][2]   - __bfloat162float(h2)),
                          __float2bfloat16(s[2*t][3]   - __bfloat162float(h3)));
            pl[2] = packh(__float2bfloat16(s[2*t+1][0] - __bfloat162float(h4)),
                          __float2bfloat16(s[2*t+1][1] - __bfloat162float(h5)));
            pl[3] = packh(__float2bfloat16(s[2*t+1][2] - __bfloat162float(h6)),
                          __float2bfloat16(s[2*t+1][3] - __bfloat162float(h7)));

            uint32_t vh[4][4], vl[4][4];
            #pragma unroll
            for (int np = 0; np < 4; np++) {
                uint32_t voff = (uint32_t)((np * 16) * (ASTR * 2) + t * 32) + lmoff;
                ldsm_x4(vh[np], sVh_b + voff);
                ldsm_x4(vl[np], sVl_b + voff);
            }
            #pragma unroll
            for (int nt = 0; nt < 8; nt++) {
                int np = nt >> 1, od = nt & 1;
                mma_bf16(o[nt], ph, vh[np][od], vh[np][od + 2]);
                mma_bf16(o[nt], ph, vl[np][od], vl[np][od + 2]);
                mma_bf16(o[nt], pl, vh[np][od], vh[np][od + 2]);
            }
        }
        __syncthreads();
    }

    // ---- finalize + write split bf16 directly to g_xhi/g_xlo [B,S,Dm] ----
    float il0 = 1.0f / l0, il1 = 1.0f / l1;
    const int row = qt * 64 + wid * 16 + (lane >> 2);
    #pragma unroll
    for (int nt = 0; nt < 8; nt++) {
        int col = h * HD + nt * 8 + (lane & 3) * 2;
        size_t i0 = ((size_t)(b * SS) + row) * DM + col;
        size_t i1 = ((size_t)(b * SS) + row + 8) * DM + col;
        float v0 = o[nt][0] * il0, v1 = o[nt][1] * il0;
        float v2 = o[nt][2] * il1, v3 = o[nt][3] * il1;
        __nv_bfloat16 hh0 = __float2bfloat16(v0);
        __nv_bfloat16 hh1 = __float2bfloat16(v1);
        __nv_bfloat16 hh2 = __float2bfloat16(v2);
        __nv_bfloat16 hh3 = __float2bfloat16(v3);
        *(__nv_bfloat162*)&g_xhi[i0] = __nv_bfloat162(hh0, hh1);
        *(__nv_bfloat162*)&g_xhi[i1] = __nv_bfloat162(hh2, hh3);
        *(__nv_bfloat162*)&g_xlo[i0] =
            __nv_bfloat162(__float2bfloat16(v0 - __bfloat162float(hh0)),
                           __float2bfloat16(v1 - __bfloat162float(hh1)));
        *(__nv_bfloat162*)&g_xlo[i1] =
            __nv_bfloat162(__float2bfloat16(v2 - __bfloat162float(hh2)),
                           __float2bfloat16(v3 - __bfloat162float(hh3)));
    }
}

// ---------------------------------------------------------------------------
extern "C" void kernel_launch(void* const* d_in, const int* in_sizes, int n_in,
                              void* d_out, int out_size)
{
    const float* x    = (const float*)d_in[0];
    const float* mask = (const float*)d_in[1];
    const float* Wq   = (const float*)d_in[2];
    const float* Wk   = (const float*)d_in[3];
    const float* Wv   = (const float*)d_in[4];
    const float* Wo   = (const float*)d_in[5];
    float* out = (float*)d_out;

    float *tq, *tk, *tv;
    __nv_bfloat16 *xhi, *xlo, *wthi, *wtlo;
    cudaGetSymbolAddress((void**)&tq, g_tq);
    cudaGetSymbolAddress((void**)&tk, g_tk);
    cudaGetSymbolAddress((void**)&tv, g_tv);
    cudaGetSymbolAddress((void**)&xhi, g_xhi);
    cudaGetSymbolAddress((void**)&xlo, g_xlo);
    cudaGetSymbolAddress((void**)&wthi, g_wthi);
    cudaGetSymbolAddress((void**)&wtlo, g_wtlo);

    cudaFuncSetAttribute(gemm_tc_kernel,
                         cudaFuncAttributeMaxDynamicSharedMemorySize, GSM_TOTAL);

    const int M = BB * SS;   // 4096
    const int NELEM = BB * SS * DM;

    // 0) prep: input split, weight transpose+split, trig table
    split_kernel<<<NELEM / 1024, 256>>>(x, xhi, xlo);
    wsplit_kernel<<<dim3(DM / 32, DM / 32, 4), 256>>>(Wq, Wk, Wv, Wo);
    trig_kernel<<<(SS * 32) / 256, 256>>>();

    // 1) fused QKV projections (HMMA split-bf16, cp.async pipeline)
    gemm_tc_kernel<<<dim3(DM / GBN, M / GBM, 3), 256, GSM_TOTAL>>>(
        xhi, xlo, wthi, wtlo, tq, tk, tv);

    // 2) RoPE (table-based) + transpose + split for Q,K; V transpose + split
    ropeqk_kernel<<<dim3((BB * NH * SS * 32) / 256, 2), 256>>>();
    vtrans_kernel<<<dim3(SS / 32, NH, BB), 256>>>();

    // 3) causal flash attention (HMMA split-bf16), writes split output
    attention_tc_kernel<<<dim3(SS / 64, BB * NH), 128>>>(mask);

    // 4) O projection (reads split written by attention)
    gemm_tc_kernel<<<dim3(DM / GBN, M / GBM, 1), 256, GSM_TOTAL>>>(
        xhi, xlo, wthi + 3 * (size_t)DM * DM, wtlo + 3 * (size_t)DM * DM,
        out, out, out);
}